// round 15
// baseline (speedup 1.0000x reference)
#include <cuda_runtime.h>
#include <cuda_fp16.h>
#include <mma.h>
#include <cstdint>

using namespace nvcuda;

#define T_TOK 16384
#define D_DIM 512
#define E_NUM 8
#define H_DIM 2048
#define CAP   16384

// tile config: CTA 256x128, 16 warps in 8x2 grid, warp tile 32x64 (R9 shape)
#define BM 256
#define BN 128
#define BK 32
#define NTHREADS 512
#define LDA 40        // fp16 elems per SMEM row (32 + 8 pad)
#define LDC 132       // fp32 epilogue staging stride (per 128-row half)
#define A_BYTES (BM * LDA * 2)            // 20480
#define B_BYTES (BN * LDA * 2)            // 10240
#define STAGE   (A_BYTES + B_BYTES)       // 30720
#define OFF_A 0
#define OFF_B A_BYTES
#define SMEM_BYTES (128 * LDC * 4)        // 67584 >= 2*STAGE = 61440

// prep kernel block ranges
#define NB_ROUTER 512                     // T_TOK/32 (4 tokens per warp)
#define NB_XSPLIT 4096                    // T_TOK*D_DIM/(256*8)
#define NB_W1     8192
#define NB_W2     8192
#define NB_TOTAL  (NB_ROUTER + NB_XSPLIT + NB_W1 + NB_W2)

// ---------------- scratch (device globals: no allocation allowed) ----------
__device__ int   g_cnt[E_NUM];
__device__ int   g_tok[E_NUM * CAP];
__device__ int   g_slot[E_NUM * CAP];
__device__ float g_gate[E_NUM * CAP];
__device__ float g_Y[(size_t)2 * T_TOK * D_DIM];
__device__ __half g_X[(size_t)T_TOK * D_DIM];
__device__ __half g_H[(size_t)E_NUM * CAP * H_DIM];
__device__ __half g_W1t[(size_t)E_NUM * H_DIM * D_DIM]; // [e][N=2048][K=512]
__device__ __half g_W2t[(size_t)E_NUM * D_DIM * H_DIM]; // [e][N=512][K=2048]

// ---------------- cp.async helpers -----------------------------------------
#define CP_ASYNC16(dst, src) \
    asm volatile("cp.async.cg.shared.global [%0], [%1], 16;" :: "r"(dst), "l"(src))
#define CP_COMMIT() asm volatile("cp.async.commit_group;" ::: "memory")
#define CP_WAIT(n)  asm volatile("cp.async.wait_group %0;" :: "n"(n) : "memory")

__device__ __forceinline__ uint32_t smem_to_u32(const void* p) {
    uint32_t a;
    asm("{ .reg .u64 t; cvta.to.shared.u64 t, %1; cvt.u32.u64 %0, t; }"
        : "=r"(a) : "l"(p));
    return a;
}

// ---------------- JAX threefry (partitionable path, key=[0,42]) ------------
__device__ __forceinline__ uint32_t rotl32(uint32_t v, int s) {
    return (v << s) | (v >> (32 - s));
}
#define TF_R4(a,b,c,d)                                     \
    x0 += x1; x1 = rotl32(x1,a); x1 ^= x0;                 \
    x0 += x1; x1 = rotl32(x1,b); x1 ^= x0;                 \
    x0 += x1; x1 = rotl32(x1,c); x1 ^= x0;                 \
    x0 += x1; x1 = rotl32(x1,d); x1 ^= x0;

__device__ __forceinline__ uint2 threefry2x32(uint32_t x0, uint32_t x1) {
    const uint32_t k0 = 0u, k1 = 42u;
    const uint32_t k2 = k0 ^ k1 ^ 0x1BD11BDAu;
    x0 += k0; x1 += k1;
    TF_R4(13,15,26, 6)  x0 += k1; x1 += k2 + 1u;
    TF_R4(17,29,16,24)  x0 += k2; x1 += k0 + 2u;
    TF_R4(13,15,26, 6)  x0 += k0; x1 += k1 + 3u;
    TF_R4(17,29,16,24)  x0 += k1; x1 += k2 + 4u;
    TF_R4(13,15,26, 6)  x0 += k2; x1 += k0 + 5u;
    return make_uint2(x0, x1);
}
__device__ __forceinline__ float jax_normal(uint32_t idx) {
    uint2 r = threefry2x32(0u, idx);
    uint32_t bits = r.x ^ r.y;
    float u01 = __uint_as_float((bits >> 9) | 0x3F800000u) - 1.0f;
    const float lo = -0.99999994f;
    float u = fmaxf(lo, u01 * 2.0f + lo);
    return 1.4142135623730951f * erfinvf(u);
}

// ---------------- pack helper: 8 fp32 -> 8 fp16 ------------------------------
__device__ __forceinline__ uint4 pack8_half(const float* f) {
    uint32_t h[4];
#pragma unroll
    for (int j = 0; j < 4; j++) {
        __half h0 = __float2half_rn(f[2 * j]);
        __half h1 = __float2half_rn(f[2 * j + 1]);
        h[j] = (uint32_t)__half_as_ushort(h0) | ((uint32_t)__half_as_ushort(h1) << 16);
    }
    return make_uint4(h[0], h[1], h[2], h[3]);
}

// ---------------- fused prologue: router | xsplit | W1t | W2t ---------------
__device__ __forceinline__ void transpose_tile(const float* __restrict__ W,
                                               __half* __restrict__ out,
                                               int K, int N, int e, int n0, int k0,
                                               int tid, float* sbuf) {
    float (*tile)[33] = (float(*)[33])sbuf;
    const float* We = W + (size_t)e * K * N;
    const int tx = tid & 31, ty = tid >> 5;   // 32 x 8
#pragma unroll
    for (int i = 0; i < 4; i++)
        tile[ty + i * 8][tx] = We[(size_t)(k0 + ty + i * 8) * N + n0 + tx];
    __syncthreads();
    const size_t base = (size_t)e * N * K;
#pragma unroll
    for (int i = 0; i < 4; i++) {
        int n = n0 + ty + i * 8, k = k0 + tx;
        out[base + (size_t)n * K + k] = __float2half_rn(tile[tx][ty + i * 8]);
    }
}

__global__ __launch_bounds__(256)
void prep_kernel(const float* __restrict__ x,
                 const float* __restrict__ Wr,
                 const float* __restrict__ br,
                 const float* __restrict__ Wn,
                 const float* __restrict__ bn,
                 const float* __restrict__ W1,
                 const float* __restrict__ W2) {
    __shared__ float sbuf[D_DIM * E_NUM * 2];   // 32 KB; aliased per branch
    const int bid = blockIdx.x;
    const int tid = threadIdx.x;

    if (bid < NB_ROUTER) {
        // ---- router: 32 tokens per block (4 per warp, weights amortized) ----
        float* sWr = sbuf;
        float* sWn = sbuf + D_DIM * E_NUM;
        for (int i = tid; i < D_DIM * E_NUM / 4; i += 256) {
            ((float4*)sWr)[i] = ((const float4*)Wr)[i];
            ((float4*)sWn)[i] = ((const float4*)Wn)[i];
        }
        __syncthreads();

        const int w = tid >> 5, lane = tid & 31;
#pragma unroll 1
        for (int it = 0; it < 4; it++) {
            const int t = bid * 32 + w * 4 + it;
            const float* xr = x + (size_t)t * D_DIM;

            float aR[E_NUM], aN[E_NUM];
#pragma unroll
            for (int e = 0; e < E_NUM; e++) { aR[e] = 0.f; aN[e] = 0.f; }
            for (int d = lane; d < D_DIM; d += 32) {
                float xv = xr[d];
                const float* wr = sWr + d * E_NUM;
                const float* wn = sWn + d * E_NUM;
#pragma unroll
                for (int e = 0; e < E_NUM; e++) {
                    aR[e] = fmaf(xv, wr[e], aR[e]);
                    aN[e] = fmaf(xv, wn[e], aN[e]);
                }
            }
#pragma unroll
            for (int e = 0; e < E_NUM; e++) {
#pragma unroll
                for (int o = 16; o > 0; o >>= 1) {
                    aR[e] += __shfl_xor_sync(0xffffffffu, aR[e], o);
                    aN[e] += __shfl_xor_sync(0xffffffffu, aN[e], o);
                }
            }
            if (lane == 0) {
                float nl[E_NUM];
#pragma unroll
                for (int e = 0; e < E_NUM; e++) {
                    float nv = aN[e] + bn[e];
                    float sp = fmaxf(nv, 0.f) + log1pf(expf(-fabsf(nv)));
                    float noise = jax_normal((uint32_t)(t * E_NUM + e));
                    nl[e] = aR[e] + br[e] + noise * sp;
                }
                int i0 = 0; float v0 = nl[0];
#pragma unroll
                for (int e = 1; e < E_NUM; e++) if (nl[e] > v0) { v0 = nl[e]; i0 = e; }
                int i1 = -1; float v1 = -3.4e38f;
#pragma unroll
                for (int e = 0; e < E_NUM; e++)
                    if (e != i0 && nl[e] > v1) { v1 = nl[e]; i1 = e; }
                float z  = expf(v1 - v0);
                float g0 = 1.f / (1.f + z);
                float g1 = z   / (1.f + z);
                int p0 = atomicAdd(&g_cnt[i0], 1);
                g_tok[i0 * CAP + p0]  = t;
                g_slot[i0 * CAP + p0] = 0;
                g_gate[i0 * CAP + p0] = g0;
                int p1 = atomicAdd(&g_cnt[i1], 1);
                g_tok[i1 * CAP + p1]  = t;
                g_slot[i1 * CAP + p1] = 1;
                g_gate[i1 * CAP + p1] = g1;
            }
        }
    } else if (bid < NB_ROUTER + NB_XSPLIT) {
        // ---- xsplit: fp32 -> fp16, 8 elems/thread ----
        const size_t i = ((size_t)(bid - NB_ROUTER) * 256 + tid) * 8;
        float f[8];
        *(float4*)&f[0] = *(const float4*)(x + i);
        *(float4*)&f[4] = *(const float4*)(x + i + 4);
        *(uint4*)(g_X + i) = pack8_half(f);
    } else if (bid < NB_ROUTER + NB_XSPLIT + NB_W1) {
        // ---- W1 transpose: [e][512][2048] -> [e][2048][512] fp16 ----
        const int idx = bid - (NB_ROUTER + NB_XSPLIT);
        const int e   = idx >> 10;
        const int rem = idx & 1023;
        const int n0  = (rem & 63) * 32;      // H_DIM/32 = 64
        const int k0  = (rem >> 6) * 32;
        transpose_tile(W1, g_W1t, D_DIM, H_DIM, e, n0, k0, tid, sbuf);
    } else {
        // ---- W2 transpose: [e][2048][512] -> [e][512][2048] fp16 ----
        const int idx = bid - (NB_ROUTER + NB_XSPLIT + NB_W1);
        const int e   = idx >> 10;
        const int rem = idx & 1023;
        const int n0  = (rem & 15) * 32;      // D_DIM/32 = 16
        const int k0  = (rem >> 4) * 32;
        transpose_tile(W2, g_W2t, H_DIM, D_DIM, e, n0, k0, tid, sbuf);
    }
}

// ---------------- wmma mainloop over one K-chunk held in SMEM ---------------
typedef wmma::fragment<wmma::matrix_a, 16, 16, 16, __half, wmma::row_major> FragA;
typedef wmma::fragment<wmma::matrix_b, 16, 16, 16, __half, wmma::col_major> FragB;
typedef wmma::fragment<wmma::accumulator, 16, 16, 16, float> FragC;

__device__ __forceinline__ void chunk_mma(const char* smem, int m0, int n0w,
                                          FragC acc[2][4]) {
    const __half* A = (const __half*)(smem + OFF_A);
    const __half* B = (const __half*)(smem + OFF_B);
#pragma unroll
    for (int ks = 0; ks < BK; ks += 16) {
        FragA a[2];
#pragma unroll
        for (int i = 0; i < 2; i++)
            wmma::load_matrix_sync(a[i], A + (m0 + 16 * i) * LDA + ks, LDA);
#pragma unroll
        for (int n = 0; n < 4; n++) {
            FragB b;
            wmma::load_matrix_sync(b, B + (n0w + 16 * n) * LDA + ks, LDA);
#pragma unroll
            for (int i = 0; i < 2; i++)
                wmma::mma_sync(acc[i][n], a[i], b, acc[i][n]);
        }
    }
}

// ---------------- GEMM1: H = relu(gather(X) @ W1[e] + b1[e]) ----------------
__global__ __launch_bounds__(NTHREADS, 1)
void gemm1_kernel(const float* __restrict__ b1) {
    const int e    = blockIdx.z;
    const int M    = g_cnt[e];
    const int row0 = blockIdx.y * BM;
    if (row0 >= M) return;
    const int n0   = blockIdx.x * BN;

    extern __shared__ char smem[];
    const uint32_t sb = smem_to_u32(smem);
    const int tid  = threadIdx.x;
    const int warp = tid >> 5;
    const int wm   = warp >> 1, wn = warp & 1;     // 8x2 warp grid
    const int m0   = wm * 32,   n0w = wn * 64;

    // A loader: 2 threads/row (256 rows), 16 halfs each
    const int arow = tid >> 1;
    const int ak   = (tid & 1) * 16;
    const int tok  = g_tok[e * CAP + row0 + arow] & (T_TOK - 1);
    const __half* ap = g_X + (size_t)tok * D_DIM + ak;
    // B loader: 4 threads/row (128 rows), 8 halfs each
    const int brow = tid >> 2;
    const int bk   = (tid & 3) * 8;
    const __half* bp = g_W1t + (size_t)e * H_DIM * D_DIM + (size_t)(n0 + brow) * D_DIM + bk;

    FragC acc[2][4];
#pragma unroll
    for (int i = 0; i < 2; i++)
#pragma unroll
        for (int n = 0; n < 4; n++) wmma::fill_fragment(acc[i][n], 0.f);

    const uint32_t soA = sb + OFF_A + (uint32_t)(arow * LDA + ak) * 2;
    const uint32_t soB = sb + OFF_B + (uint32_t)(brow * LDA + bk) * 2;

#define G1_LOAD(k0, st) do {                                                \
        uint32_t a_ = soA + (st) * STAGE;                                   \
        uint32_t b_ = soB + (st) * STAGE;                                   \
        CP_ASYNC16(a_,      ap + (k0));                                     \
        CP_ASYNC16(a_ + 16, ap + (k0) + 8);                                 \
        CP_ASYNC16(b_,      bp + (k0));                                     \
        CP_COMMIT();                                                        \
    } while (0)

    G1_LOAD(0, 0);
    const int NC = D_DIM / BK;   // 16
#pragma unroll 1
    for (int c = 0; c < NC; c++) {
        const int st = c & 1;
        if (c + 1 < NC) { G1_LOAD((c + 1) * BK, st ^ 1); CP_WAIT(1); }
        else            { CP_WAIT(0); }
        __syncthreads();
        chunk_mma(smem + st * STAGE, m0, n0w, acc);
        __syncthreads();
    }

    // epilogue in two 128-row halves through the 67.5 KB staging buffer
    float* Cs = (float*)smem;
    const float* b1e = b1 + e * H_DIM + n0;
#pragma unroll 1
    for (int half = 0; half < 2; half++) {
        if ((wm >> 2) == half) {
#pragma unroll
            for (int i = 0; i < 2; i++)
#pragma unroll
                for (int n = 0; n < 4; n++)
                    wmma::store_matrix_sync(
                        Cs + (m0 - half * 128 + 16 * i) * LDC + n0w + 16 * n,
                        acc[i][n], LDC, wmma::mem_row_major);
        }
        __syncthreads();
        const int erow = tid >> 2;
        const int ecol = (tid & 3) * 32;
        const size_t hbase = ((size_t)e * CAP + row0 + half * 128 + erow) * H_DIM + n0 + ecol;
#pragma unroll
        for (int q = 0; q < 4; q++) {
            float f[8];
#pragma unroll
            for (int j = 0; j < 8; j++)
                f[j] = fmaxf(Cs[erow * LDC + ecol + q * 8 + j] + __ldg(b1e + ecol + q * 8 + j), 0.f);
            *(uint4*)(g_H + hbase + q * 8) = pack8_half(f);
        }
        __syncthreads();
    }
}

// ---------------- GEMM2: Y[slot][tok] = gate * (H @ W2[e] + b2[e]) ----------
__global__ __launch_bounds__(NTHREADS, 1)
void gemm2_kernel(const float* __restrict__ b2) {
    const int e    = blockIdx.z;
    const int M    = g_cnt[e];
    const int row0 = blockIdx.y * BM;
    if (row0 >= M) return;
    const int n0   = blockIdx.x * BN;

    extern __shared__ char smem[];
    const uint32_t sb = smem_to_u32(smem);
    const int tid  = threadIdx.x;
    const int warp = tid >> 5;
    const int wm   = warp >> 1, wn = warp & 1;
    const int m0   = wm * 32,   n0w = wn * 64;

    const int arow = tid >> 1;
    const int ak   = (tid & 1) * 16;
    const __half* ap = g_H + ((size_t)e * CAP + row0 + arow) * H_DIM + ak;
    const int brow = tid >> 2;
    const int bk   = (tid & 3) * 8;
    const __half* bp = g_W2t + (size_t)e * D_DIM * H_DIM + (size_t)(n0 + brow) * H_DIM + bk;

    FragC acc[2][4];
#pragma unroll
    for (int i = 0; i < 2; i++)
#pragma unroll
        for (int n = 0; n < 4; n++) wmma::fill_fragment(acc[i][n], 0.f);

    const uint32_t soA = sb + OFF_A + (uint32_t)(arow * LDA + ak) * 2;
    const uint32_t soB = sb + OFF_B + (uint32_t)(brow * LDA + bk) * 2;

#define G2_LOAD(k0, st) do {                                                \
        uint32_t a_ = soA + (st) * STAGE;                                   \
        uint32_t b_ = soB + (st) * STAGE;                                   \
        CP_ASYNC16(a_,      ap + (k0));                                     \
        CP_ASYNC16(a_ + 16, ap + (k0) + 8);                                 \
        CP_ASYNC16(b_,      bp + (k0));                                     \
        CP_COMMIT();                                                        \
    } while (0)

    G2_LOAD(0, 0);
    const int NC = H_DIM / BK;   // 64
#pragma unroll 1
    for (int c = 0; c < NC; c++) {
        const int st = c & 1;
        if (c + 1 < NC) { G2_LOAD((c + 1) * BK, st ^ 1); CP_WAIT(1); }
        else            { CP_WAIT(0); }
        __syncthreads();
        chunk_mma(smem + st * STAGE, m0, n0w, acc);
        __syncthreads();
    }

    float* Cs = (float*)smem;
    const float* b2e = b2 + e * D_DIM + n0;
#pragma unroll 1
    for (int half = 0; half < 2; half++) {
        if ((wm >> 2) == half) {
#pragma unroll
            for (int i = 0; i < 2; i++)
#pragma unroll
                for (int n = 0; n < 4; n++)
                    wmma::store_matrix_sync(
                        Cs + (m0 - half * 128 + 16 * i) * LDC + n0w + 16 * n,
                        acc[i][n], LDC, wmma::mem_row_major);
        }
        __syncthreads();
        const int erow = tid >> 2;
        const int ecol = (tid & 3) * 32;
        const int grow = row0 + half * 128 + erow;
        if (grow < M) {
            const int   tok  = g_tok[e * CAP + grow];
            const int   slot = g_slot[e * CAP + grow];
            const float gate = g_gate[e * CAP + grow];
            float* yp = g_Y + ((size_t)slot * T_TOK + tok) * D_DIM + n0 + ecol;
#pragma unroll
            for (int q = 0; q < 8; q++) {
                float4 v;
                v.x = gate * (Cs[erow * LDC + ecol + q * 4 + 0] + __ldg(b2e + ecol + q * 4 + 0));
                v.y = gate * (Cs[erow * LDC + ecol + q * 4 + 1] + __ldg(b2e + ecol + q * 4 + 1));
                v.z = gate * (Cs[erow * LDC + ecol + q * 4 + 2] + __ldg(b2e + ecol + q * 4 + 2));
                v.w = gate * (Cs[erow * LDC + ecol + q * 4 + 3] + __ldg(b2e + ecol + q * 4 + 3));
                *(float4*)(yp + q * 4) = v;
            }
        }
        __syncthreads();
    }
}

// ---------------- combine: out = Y0 + Y1 ------------------------------------
__global__ __launch_bounds__(256)
void combine_kernel(float* __restrict__ out) {
    const size_t i = ((size_t)blockIdx.x * 256 + threadIdx.x) * 4;
    float4 a = *(const float4*)(g_Y + i);
    float4 b = *(const float4*)(g_Y + (size_t)T_TOK * D_DIM + i);
    float4 v;
    v.x = a.x + b.x; v.y = a.y + b.y; v.z = a.z + b.z; v.w = a.w + b.w;
    *(float4*)(out + i) = v;
}

// ---------------- launch ---------------------------------------------------
extern "C" void kernel_launch(void* const* d_in, const int* in_sizes, int n_in,
                              void* d_out, int out_size) {
    const float* x  = (const float*)d_in[0];
    const float* Wr = (const float*)d_in[1];
    const float* br = (const float*)d_in[2];
    const float* Wn = (const float*)d_in[3];
    const float* bn = (const float*)d_in[4];
    const float* W1 = (const float*)d_in[5];
    const float* b1 = (const float*)d_in[6];
    const float* W2 = (const float*)d_in[7];
    const float* b2 = (const float*)d_in[8];
    float* out = (float*)d_out;

    cudaFuncSetAttribute(gemm1_kernel, cudaFuncAttributeMaxDynamicSharedMemorySize, SMEM_BYTES);
    cudaFuncSetAttribute(gemm2_kernel, cudaFuncAttributeMaxDynamicSharedMemorySize, SMEM_BYTES);

    void* cntp = nullptr;
    cudaGetSymbolAddress(&cntp, g_cnt);
    cudaMemsetAsync(cntp, 0, sizeof(int) * E_NUM, 0);

    // fused prologue: router + X fp16 prestage + both weight transposes
    prep_kernel<<<NB_TOTAL, 256>>>(x, Wr, br, Wn, bn, W1, W2);

    dim3 grid1(H_DIM / BN, CAP / BM, E_NUM);
    gemm1_kernel<<<grid1, NTHREADS, SMEM_BYTES>>>(b1);

    dim3 grid2(D_DIM / BN, CAP / BM, E_NUM);
    gemm2_kernel<<<grid2, NTHREADS, SMEM_BYTES>>>(b2);

    combine_kernel<<<T_TOK * D_DIM / (256 * 4), 256>>>(out);
}

// round 16
// speedup vs baseline: 1.0812x; 1.0812x over previous
#include <cuda_runtime.h>
#include <cuda_fp16.h>
#include <mma.h>
#include <cstdint>

using namespace nvcuda;

#define T_TOK 16384
#define D_DIM 512
#define E_NUM 8
#define H_DIM 2048
#define CAP   16384

// tile config (R9/R13-proven)
#define BM 128
#define BN 128
#define BK 32
#define LDA 40        // fp16 elems per SMEM row (32 + 8 pad)
#define LDC 132       // fp32 epilogue staging stride
#define STAGE 20480   // bytes per stage: 2 tiles x 128 x 40 x 2B
#define SMEM_BYTES (BM * LDC * 4)   // 67584 >= 2*STAGE = 40960
#define OFF_A 0
#define OFF_B 10240

// prep kernel block ranges (W2 transpose moved into gemm1 z-slice)
#define NB_ROUTER 2048                    // T_TOK/8
#define NB_XSPLIT 4096                    // T_TOK*D_DIM/(256*8)
#define NB_W1     8192                    // (H_DIM/32)*(D_DIM/32)*E_NUM
#define NB_TOTAL  (NB_ROUTER + NB_XSPLIT + NB_W1)

// ---------------- scratch (device globals: no allocation allowed) ----------
__device__ int   g_cnt[E_NUM];
__device__ int   g_tok[E_NUM * CAP];
__device__ int   g_slot[E_NUM * CAP];
__device__ float g_gate[E_NUM * CAP];
__device__ float g_Y[(size_t)2 * T_TOK * D_DIM];
__device__ __half g_X[(size_t)T_TOK * D_DIM];
__device__ __half g_H[(size_t)E_NUM * CAP * H_DIM];
__device__ __half g_W1t[(size_t)E_NUM * H_DIM * D_DIM]; // [e][N=2048][K=512]
__device__ __half g_W2t[(size_t)E_NUM * D_DIM * H_DIM]; // [e][N=512][K=2048]

// ---------------- cp.async helpers -----------------------------------------
#define CP_ASYNC16(dst, src) \
    asm volatile("cp.async.cg.shared.global [%0], [%1], 16;" :: "r"(dst), "l"(src))
#define CP_COMMIT() asm volatile("cp.async.commit_group;" ::: "memory")
#define CP_WAIT(n)  asm volatile("cp.async.wait_group %0;" :: "n"(n) : "memory")

__device__ __forceinline__ uint32_t smem_to_u32(const void* p) {
    uint32_t a;
    asm("{ .reg .u64 t; cvta.to.shared.u64 t, %1; cvt.u32.u64 %0, t; }"
        : "=r"(a) : "l"(p));
    return a;
}

// ---------------- JAX threefry (partitionable path, key=[0,42]) ------------
__device__ __forceinline__ uint32_t rotl32(uint32_t v, int s) {
    return (v << s) | (v >> (32 - s));
}
#define TF_R4(a,b,c,d)                                     \
    x0 += x1; x1 = rotl32(x1,a); x1 ^= x0;                 \
    x0 += x1; x1 = rotl32(x1,b); x1 ^= x0;                 \
    x0 += x1; x1 = rotl32(x1,c); x1 ^= x0;                 \
    x0 += x1; x1 = rotl32(x1,d); x1 ^= x0;

__device__ __forceinline__ uint2 threefry2x32(uint32_t x0, uint32_t x1) {
    const uint32_t k0 = 0u, k1 = 42u;
    const uint32_t k2 = k0 ^ k1 ^ 0x1BD11BDAu;
    x0 += k0; x1 += k1;
    TF_R4(13,15,26, 6)  x0 += k1; x1 += k2 + 1u;
    TF_R4(17,29,16,24)  x0 += k2; x1 += k0 + 2u;
    TF_R4(13,15,26, 6)  x0 += k0; x1 += k1 + 3u;
    TF_R4(17,29,16,24)  x0 += k1; x1 += k2 + 4u;
    TF_R4(13,15,26, 6)  x0 += k2; x1 += k0 + 5u;
    return make_uint2(x0, x1);
}
__device__ __forceinline__ float jax_normal(uint32_t idx) {
    uint2 r = threefry2x32(0u, idx);
    uint32_t bits = r.x ^ r.y;
    float u01 = __uint_as_float((bits >> 9) | 0x3F800000u) - 1.0f;
    const float lo = -0.99999994f;
    float u = fmaxf(lo, u01 * 2.0f + lo);
    return 1.4142135623730951f * erfinvf(u);
}

// ---------------- pack helper: 8 fp32 -> 8 fp16 ------------------------------
__device__ __forceinline__ uint4 pack8_half(const float* f) {
    uint32_t h[4];
#pragma unroll
    for (int j = 0; j < 4; j++) {
        __half h0 = __float2half_rn(f[2 * j]);
        __half h1 = __float2half_rn(f[2 * j + 1]);
        h[j] = (uint32_t)__half_as_ushort(h0) | ((uint32_t)__half_as_ushort(h1) << 16);
    }
    return make_uint4(h[0], h[1], h[2], h[3]);
}

// ---------------- 32x32 transpose tile: fp32 [K][N] -> fp16 [N][K] ----------
__device__ __forceinline__ void transpose_tile(const float* __restrict__ W,
                                               __half* __restrict__ out,
                                               int K, int N, int e, int n0, int k0,
                                               int tid, float* sbuf) {
    float (*tile)[33] = (float(*)[33])sbuf;
    const float* We = W + (size_t)e * K * N;
    const int tx = tid & 31, ty = tid >> 5;   // 32 x 8
#pragma unroll
    for (int i = 0; i < 4; i++)
        tile[ty + i * 8][tx] = We[(size_t)(k0 + ty + i * 8) * N + n0 + tx];
    __syncthreads();
    const size_t base = (size_t)e * N * K;
#pragma unroll
    for (int i = 0; i < 4; i++) {
        int n = n0 + ty + i * 8, k = k0 + tx;
        out[base + (size_t)n * K + k] = __float2half_rn(tile[tx][ty + i * 8]);
    }
}

// ---------------- fused prologue: router | xsplit | W1t ---------------------
__global__ __launch_bounds__(256)
void prep_kernel(const float* __restrict__ x,
                 const float* __restrict__ Wr,
                 const float* __restrict__ br,
                 const float* __restrict__ Wn,
                 const float* __restrict__ bn,
                 const float* __restrict__ W1) {
    __shared__ float sbuf[D_DIM * E_NUM * 2];   // 32 KB; aliased per branch
    const int bid = blockIdx.x;
    const int tid = threadIdx.x;

    if (bid < NB_ROUTER) {
        // ---- router: 8 tokens per block ----
        float* sWr = sbuf;
        float* sWn = sbuf + D_DIM * E_NUM;
        for (int i = tid; i < D_DIM * E_NUM / 4; i += 256) {
            ((float4*)sWr)[i] = ((const float4*)Wr)[i];
            ((float4*)sWn)[i] = ((const float4*)Wn)[i];
        }
        __syncthreads();

        const int w = tid >> 5, lane = tid & 31;
        const int t = bid * 8 + w;
        const float* xr = x + (size_t)t * D_DIM;

        float aR[E_NUM], aN[E_NUM];
#pragma unroll
        for (int e = 0; e < E_NUM; e++) { aR[e] = 0.f; aN[e] = 0.f; }
        for (int d = lane; d < D_DIM; d += 32) {
            float xv = xr[d];
            const float* wr = sWr + d * E_NUM;
            const float* wn = sWn + d * E_NUM;
#pragma unroll
            for (int e = 0; e < E_NUM; e++) {
                aR[e] = fmaf(xv, wr[e], aR[e]);
                aN[e] = fmaf(xv, wn[e], aN[e]);
            }
        }
#pragma unroll
        for (int e = 0; e < E_NUM; e++) {
#pragma unroll
            for (int o = 16; o > 0; o >>= 1) {
                aR[e] += __shfl_xor_sync(0xffffffffu, aR[e], o);
                aN[e] += __shfl_xor_sync(0xffffffffu, aN[e], o);
            }
        }
        if (lane == 0) {
            float nl[E_NUM];
#pragma unroll
            for (int e = 0; e < E_NUM; e++) {
                float nv = aN[e] + bn[e];
                float sp = fmaxf(nv, 0.f) + log1pf(expf(-fabsf(nv)));
                float noise = jax_normal((uint32_t)(t * E_NUM + e));
                nl[e] = aR[e] + br[e] + noise * sp;
            }
            int i0 = 0; float v0 = nl[0];
#pragma unroll
            for (int e = 1; e < E_NUM; e++) if (nl[e] > v0) { v0 = nl[e]; i0 = e; }
            int i1 = -1; float v1 = -3.4e38f;
#pragma unroll
            for (int e = 0; e < E_NUM; e++)
                if (e != i0 && nl[e] > v1) { v1 = nl[e]; i1 = e; }
            float z  = expf(v1 - v0);
            float g0 = 1.f / (1.f + z);
            float g1 = z   / (1.f + z);
            int p0 = atomicAdd(&g_cnt[i0], 1);
            g_tok[i0 * CAP + p0]  = t;
            g_slot[i0 * CAP + p0] = 0;
            g_gate[i0 * CAP + p0] = g0;
            int p1 = atomicAdd(&g_cnt[i1], 1);
            g_tok[i1 * CAP + p1]  = t;
            g_slot[i1 * CAP + p1] = 1;
            g_gate[i1 * CAP + p1] = g1;
        }
    } else if (bid < NB_ROUTER + NB_XSPLIT) {
        // ---- xsplit: fp32 -> fp16, 8 elems/thread ----
        const size_t i = ((size_t)(bid - NB_ROUTER) * 256 + tid) * 8;
        float f[8];
        *(float4*)&f[0] = *(const float4*)(x + i);
        *(float4*)&f[4] = *(const float4*)(x + i + 4);
        *(uint4*)(g_X + i) = pack8_half(f);
    } else {
        // ---- W1 transpose: [e][512][2048] -> [e][2048][512] fp16 ----
        const int idx = bid - (NB_ROUTER + NB_XSPLIT);
        const int e   = idx >> 10;            // / (64*16)
        const int rem = idx & 1023;
        const int n0  = (rem & 63) * 32;      // H_DIM/32 = 64
        const int k0  = (rem >> 6) * 32;
        transpose_tile(W1, g_W1t, D_DIM, H_DIM, e, n0, k0, tid, sbuf);
    }
}

// ---------------- wmma mainloop over one K-chunk held in SMEM ---------------
typedef wmma::fragment<wmma::matrix_a, 16, 16, 16, __half, wmma::row_major> FragA;
typedef wmma::fragment<wmma::matrix_b, 16, 16, 16, __half, wmma::col_major> FragB;
typedef wmma::fragment<wmma::accumulator, 16, 16, 16, float> FragC;

__device__ __forceinline__ void chunk_mma(const char* smem, int m0, int n0w,
                                          FragC acc[2][4]) {
    const __half* A = (const __half*)(smem + OFF_A);
    const __half* B = (const __half*)(smem + OFF_B);
#pragma unroll
    for (int ks = 0; ks < BK; ks += 16) {
        FragA a[2];
#pragma unroll
        for (int i = 0; i < 2; i++)
            wmma::load_matrix_sync(a[i], A + (m0 + 16 * i) * LDA + ks, LDA);
#pragma unroll
        for (int n = 0; n < 4; n++) {
            FragB b;
            wmma::load_matrix_sync(b, B + (n0w + 16 * n) * LDA + ks, LDA);
#pragma unroll
            for (int i = 0; i < 2; i++)
                wmma::mma_sync(acc[i][n], a[i], b, acc[i][n]);
        }
    }
}

// ---------------- GEMM1 (+ z==8 slice: W2 transpose) ------------------------
__global__ __launch_bounds__(256)
void gemm1_kernel(const float* __restrict__ b1, const float* __restrict__ W2) {
    extern __shared__ char smem[];

    if (blockIdx.z == E_NUM) {
        // ---- W2 transpose slice: [e][2048][512] -> [e][512][2048] fp16 ----
        // 2048 blocks (y*16+x in 0..2047), 4 tiles each = 8192 tiles
        const int bblk = blockIdx.y * (H_DIM / BN) + blockIdx.x;  // 0..2047
        const int tid  = threadIdx.x;
#pragma unroll 1
        for (int i = 0; i < 4; i++) {
            const int t   = bblk * 4 + i;
            const int e   = t >> 10;
            const int rem = t & 1023;
            const int n0  = (rem & 15) * 32;      // D_DIM/32 = 16
            const int k0  = (rem >> 4) * 32;
            transpose_tile(W2, g_W2t, H_DIM, D_DIM, e, n0, k0, tid, (float*)smem);
            __syncthreads();
        }
        return;
    }

    const int e    = blockIdx.z;
    const int M    = g_cnt[e];
    const int row0 = blockIdx.y * BM;
    if (row0 >= M) return;
    const int n0   = blockIdx.x * BN;

    const uint32_t sb = smem_to_u32(smem);
    const int tid  = threadIdx.x;
    const int warp = tid >> 5;
    const int wm   = warp >> 1, wn = warp & 1;     // 4x2 warp grid
    const int m0   = wm * 32,   n0w = wn * 64;

    const int lrow = tid >> 1;                     // loader row 0..127
    const int lk   = (tid & 1) * 16;               // loader col offset in chunk

    const int tok = g_tok[e * CAP + row0 + lrow];
    const __half* ap = g_X + (size_t)tok * D_DIM + lk;
    const __half* bp = g_W1t + (size_t)e * H_DIM * D_DIM + (size_t)(n0 + lrow) * D_DIM + lk;

    FragC acc[2][4];
#pragma unroll
    for (int i = 0; i < 2; i++)
#pragma unroll
        for (int n = 0; n < 4; n++) wmma::fill_fragment(acc[i][n], 0.f);

    const uint32_t so = sb + (uint32_t)(lrow * LDA + lk) * 2;

#define G1_LOAD(k0, st) do {                                                \
        uint32_t d_ = so + (st) * STAGE;                                    \
        CP_ASYNC16(d_ + OFF_A,      ap + (k0));                             \
        CP_ASYNC16(d_ + OFF_A + 16, ap + (k0) + 8);                         \
        CP_ASYNC16(d_ + OFF_B,      bp + (k0));                             \
        CP_ASYNC16(d_ + OFF_B + 16, bp + (k0) + 8);                         \
        CP_COMMIT();                                                        \
    } while (0)

    G1_LOAD(0, 0);
    const int NC = D_DIM / BK;   // 16
#pragma unroll 1
    for (int c = 0; c < NC; c++) {
        const int st = c & 1;
        if (c + 1 < NC) { G1_LOAD((c + 1) * BK, st ^ 1); CP_WAIT(1); }
        else            { CP_WAIT(0); }
        __syncthreads();
        chunk_mma(smem + st * STAGE, m0, n0w, acc);
        __syncthreads();
    }

    // epilogue: stage accum to SMEM fp32, then relu+bias -> fp16 H
    float* Cs = (float*)smem;
#pragma unroll
    for (int i = 0; i < 2; i++)
#pragma unroll
        for (int n = 0; n < 4; n++)
            wmma::store_matrix_sync(Cs + (m0 + 16 * i) * LDC + n0w + 16 * n,
                                    acc[i][n], LDC, wmma::mem_row_major);
    __syncthreads();

    const int erow = tid >> 1;
    const int ecol = (tid & 1) * 64;
    const float* b1e = b1 + e * H_DIM + n0 + ecol;
    const size_t hbase = ((size_t)e * CAP + row0 + erow) * H_DIM + n0 + ecol;
#pragma unroll
    for (int q = 0; q < 8; q++) {
        float f[8];
#pragma unroll
        for (int j = 0; j < 8; j++)
            f[j] = fmaxf(Cs[erow * LDC + ecol + q * 8 + j] + __ldg(b1e + q * 8 + j), 0.f);
        *(uint4*)(g_H + hbase + q * 8) = pack8_half(f);
    }
}

// ---------------- GEMM2: Y[slot][tok] = gate * (H @ W2[e] + b2[e]) ----------
__global__ __launch_bounds__(256)
void gemm2_kernel(const float* __restrict__ b2) {
    const int e    = blockIdx.z;
    const int M    = g_cnt[e];
    const int row0 = blockIdx.y * BM;
    if (row0 >= M) return;
    const int n0   = blockIdx.x * BN;

    extern __shared__ char smem[];
    const uint32_t sb = smem_to_u32(smem);
    const int tid  = threadIdx.x;
    const int warp = tid >> 5;
    const int wm   = warp >> 1, wn = warp & 1;
    const int m0   = wm * 32,   n0w = wn * 64;

    const int lrow = tid >> 1;
    const int lk   = (tid & 1) * 16;

    const __half* ap = g_H + ((size_t)e * CAP + row0 + lrow) * H_DIM + lk;
    const __half* bp = g_W2t + (size_t)e * D_DIM * H_DIM + (size_t)(n0 + lrow) * H_DIM + lk;

    FragC acc[2][4];
#pragma unroll
    for (int i = 0; i < 2; i++)
#pragma unroll
        for (int n = 0; n < 4; n++) wmma::fill_fragment(acc[i][n], 0.f);

    const uint32_t so = sb + (uint32_t)(lrow * LDA + lk) * 2;

#define G2_LOAD(k0, st) do {                                                \
        uint32_t d_ = so + (st) * STAGE;                                    \
        CP_ASYNC16(d_ + OFF_A,      ap + (k0));                             \
        CP_ASYNC16(d_ + OFF_A + 16, ap + (k0) + 8);                         \
        CP_ASYNC16(d_ + OFF_B,      bp + (k0));                             \
        CP_ASYNC16(d_ + OFF_B + 16, bp + (k0) + 8);                         \
        CP_COMMIT();                                                        \
    } while (0)

    G2_LOAD(0, 0);
    const int NC = H_DIM / BK;   // 64
#pragma unroll 1
    for (int c = 0; c < NC; c++) {
        const int st = c & 1;
        if (c + 1 < NC) { G2_LOAD((c + 1) * BK, st ^ 1); CP_WAIT(1); }
        else            { CP_WAIT(0); }
        __syncthreads();
        chunk_mma(smem + st * STAGE, m0, n0w, acc);
        __syncthreads();
    }

    float* Cs = (float*)smem;
#pragma unroll
    for (int i = 0; i < 2; i++)
#pragma unroll
        for (int n = 0; n < 4; n++)
            wmma::store_matrix_sync(Cs + (m0 + 16 * i) * LDC + n0w + 16 * n,
                                    acc[i][n], LDC, wmma::mem_row_major);
    __syncthreads();

    const int erow = tid >> 1;
    const int ecol = (tid & 1) * 64;
    if (row0 + erow < M) {
        const int   tok  = g_tok[e * CAP + row0 + erow];
        const int   slot = g_slot[e * CAP + row0 + erow];
        const float gate = g_gate[e * CAP + row0 + erow];
        const float* b2e = b2 + e * D_DIM + n0 + ecol;
        float* yp = g_Y + ((size_t)slot * T_TOK + tok) * D_DIM + n0 + ecol;
#pragma unroll
        for (int q = 0; q < 16; q++) {
            float4 v;
            v.x = gate * (Cs[erow * LDC + ecol + q * 4 + 0] + __ldg(b2e + q * 4 + 0));
            v.y = gate * (Cs[erow * LDC + ecol + q * 4 + 1] + __ldg(b2e + q * 4 + 1));
            v.z = gate * (Cs[erow * LDC + ecol + q * 4 + 2] + __ldg(b2e + q * 4 + 2));
            v.w = gate * (Cs[erow * LDC + ecol + q * 4 + 3] + __ldg(b2e + q * 4 + 3));
            *(float4*)(yp + q * 4) = v;
        }
    }
}

// ---------------- combine: out = Y0 + Y1 ------------------------------------
__global__ __launch_bounds__(256)
void combine_kernel(float* __restrict__ out) {
    const size_t i = ((size_t)blockIdx.x * 256 + threadIdx.x) * 4;
    float4 a = *(const float4*)(g_Y + i);
    float4 b = *(const float4*)(g_Y + (size_t)T_TOK * D_DIM + i);
    float4 v;
    v.x = a.x + b.x; v.y = a.y + b.y; v.z = a.z + b.z; v.w = a.w + b.w;
    *(float4*)(out + i) = v;
}

// ---------------- launch ---------------------------------------------------
extern "C" void kernel_launch(void* const* d_in, const int* in_sizes, int n_in,
                              void* d_out, int out_size) {
    const float* x  = (const float*)d_in[0];
    const float* Wr = (const float*)d_in[1];
    const float* br = (const float*)d_in[2];
    const float* Wn = (const float*)d_in[3];
    const float* bn = (const float*)d_in[4];
    const float* W1 = (const float*)d_in[5];
    const float* b1 = (const float*)d_in[6];
    const float* W2 = (const float*)d_in[7];
    const float* b2 = (const float*)d_in[8];
    float* out = (float*)d_out;

    cudaFuncSetAttribute(gemm1_kernel, cudaFuncAttributeMaxDynamicSharedMemorySize, SMEM_BYTES);
    cudaFuncSetAttribute(gemm2_kernel, cudaFuncAttributeMaxDynamicSharedMemorySize, SMEM_BYTES);

    void* cntp = nullptr;
    cudaGetSymbolAddress(&cntp, g_cnt);
    cudaMemsetAsync(cntp, 0, sizeof(int) * E_NUM, 0);

    // fused prologue: router + X fp16 prestage + W1 transpose
    prep_kernel<<<NB_TOTAL, 256>>>(x, Wr, br, Wn, bn, W1);

    // gemm1 + W2 transpose folded in as z == E_NUM slice
    dim3 grid1(H_DIM / BN, CAP / BM, E_NUM + 1);
    gemm1_kernel<<<grid1, 256, SMEM_BYTES>>>(b1, W2);

    dim3 grid2(D_DIM / BN, CAP / BM, E_NUM);
    gemm2_kernel<<<grid2, 256, SMEM_BYTES>>>(b2);

    combine_kernel<<<T_TOK * D_DIM / (256 * 4), 256>>>(out);
}

// round 17
// speedup vs baseline: 1.1592x; 1.0721x over previous
#include <cuda_runtime.h>
#include <cuda_fp16.h>
#include <mma.h>
#include <cstdint>

using namespace nvcuda;

#define T_TOK 16384
#define D_DIM 512
#define E_NUM 8
#define H_DIM 2048
#define CAP   16384

// tile config (R9/R13-proven)
#define BM 128
#define BN 128
#define BK 32
#define LDA 40        // fp16 elems per SMEM row (32 + 8 pad)
#define LDC 132       // fp32 epilogue staging stride
#define STAGE 20480   // bytes per stage: 2 tiles x 128 x 40 x 2B
#define SMEM_BYTES (BM * LDC * 4)   // 67584 >= 2*STAGE = 40960
#define OFF_A 0
#define OFF_B 10240

// prep kernel block ranges (R13)
#define NB_ROUTER 2048                    // T_TOK/8
#define NB_XSPLIT 4096                    // T_TOK*D_DIM/(256*8)
#define NB_W1     8192                    // (H_DIM/32)*(D_DIM/32)*E_NUM
#define NB_W2     8192                    // (D_DIM/32)*(H_DIM/32)*E_NUM
#define NB_TOTAL  (NB_ROUTER + NB_XSPLIT + NB_W1 + NB_W2)

// ---------------- scratch (device globals: no allocation allowed) ----------
__device__ int   g_cnt[E_NUM];
__device__ int   g_tok[E_NUM * CAP];
__device__ int   g_slot[E_NUM * CAP];
__device__ float g_gate[E_NUM * CAP];
__device__ __half g_Yh[(size_t)2 * T_TOK * D_DIM];   // fp16 two-slot staging
__device__ __half g_X[(size_t)T_TOK * D_DIM];
__device__ __half g_H[(size_t)E_NUM * CAP * H_DIM];
__device__ __half g_W1t[(size_t)E_NUM * H_DIM * D_DIM]; // [e][N=2048][K=512]
__device__ __half g_W2t[(size_t)E_NUM * D_DIM * H_DIM]; // [e][N=512][K=2048]

// ---------------- cp.async helpers -----------------------------------------
#define CP_ASYNC16(dst, src) \
    asm volatile("cp.async.cg.shared.global [%0], [%1], 16;" :: "r"(dst), "l"(src))
#define CP_ASYNC16_CA(dst, src) \
    asm volatile("cp.async.ca.shared.global [%0], [%1], 16;" :: "r"(dst), "l"(src))
#define CP_COMMIT() asm volatile("cp.async.commit_group;" ::: "memory")
#define CP_WAIT(n)  asm volatile("cp.async.wait_group %0;" :: "n"(n) : "memory")

__device__ __forceinline__ uint32_t smem_to_u32(const void* p) {
    uint32_t a;
    asm("{ .reg .u64 t; cvta.to.shared.u64 t, %1; cvt.u32.u64 %0, t; }"
        : "=r"(a) : "l"(p));
    return a;
}

// ---------------- JAX threefry (partitionable path, key=[0,42]) ------------
__device__ __forceinline__ uint32_t rotl32(uint32_t v, int s) {
    return (v << s) | (v >> (32 - s));
}
#define TF_R4(a,b,c,d)                                     \
    x0 += x1; x1 = rotl32(x1,a); x1 ^= x0;                 \
    x0 += x1; x1 = rotl32(x1,b); x1 ^= x0;                 \
    x0 += x1; x1 = rotl32(x1,c); x1 ^= x0;                 \
    x0 += x1; x1 = rotl32(x1,d); x1 ^= x0;

__device__ __forceinline__ uint2 threefry2x32(uint32_t x0, uint32_t x1) {
    const uint32_t k0 = 0u, k1 = 42u;
    const uint32_t k2 = k0 ^ k1 ^ 0x1BD11BDAu;
    x0 += k0; x1 += k1;
    TF_R4(13,15,26, 6)  x0 += k1; x1 += k2 + 1u;
    TF_R4(17,29,16,24)  x0 += k2; x1 += k0 + 2u;
    TF_R4(13,15,26, 6)  x0 += k0; x1 += k1 + 3u;
    TF_R4(17,29,16,24)  x0 += k1; x1 += k2 + 4u;
    TF_R4(13,15,26, 6)  x0 += k2; x1 += k0 + 5u;
    return make_uint2(x0, x1);
}
__device__ __forceinline__ float jax_normal(uint32_t idx) {
    uint2 r = threefry2x32(0u, idx);
    uint32_t bits = r.x ^ r.y;
    float u01 = __uint_as_float((bits >> 9) | 0x3F800000u) - 1.0f;
    const float lo = -0.99999994f;
    float u = fmaxf(lo, u01 * 2.0f + lo);
    return 1.4142135623730951f * erfinvf(u);
}

// ---------------- pack helper: 8 fp32 -> 8 fp16 ------------------------------
__device__ __forceinline__ uint4 pack8_half(const float* f) {
    uint32_t h[4];
#pragma unroll
    for (int j = 0; j < 4; j++) {
        __half h0 = __float2half_rn(f[2 * j]);
        __half h1 = __float2half_rn(f[2 * j + 1]);
        h[j] = (uint32_t)__half_as_ushort(h0) | ((uint32_t)__half_as_ushort(h1) << 16);
    }
    return make_uint4(h[0], h[1], h[2], h[3]);
}

// ---------------- 32x32 transpose tile: fp32 [K][N] -> fp16 [N][K] ----------
__device__ __forceinline__ void transpose_tile(const float* __restrict__ W,
                                               __half* __restrict__ out,
                                               int K, int N, int e, int n0, int k0,
                                               int tid, float* sbuf) {
    float (*tile)[33] = (float(*)[33])sbuf;
    const float* We = W + (size_t)e * K * N;
    const int tx = tid & 31, ty = tid >> 5;   // 32 x 8
#pragma unroll
    for (int i = 0; i < 4; i++)
        tile[ty + i * 8][tx] = We[(size_t)(k0 + ty + i * 8) * N + n0 + tx];
    __syncthreads();
    const size_t base = (size_t)e * N * K;
#pragma unroll
    for (int i = 0; i < 4; i++) {
        int n = n0 + ty + i * 8, k = k0 + tx;
        out[base + (size_t)n * K + k] = __float2half_rn(tile[tx][ty + i * 8]);
    }
}

// ---------------- fused prologue: router | xsplit | W1t | W2t ---------------
__global__ __launch_bounds__(256)
void prep_kernel(const float* __restrict__ x,
                 const float* __restrict__ Wr,
                 const float* __restrict__ br,
                 const float* __restrict__ Wn,
                 const float* __restrict__ bn,
                 const float* __restrict__ W1,
                 const float* __restrict__ W2) {
    __shared__ float sbuf[D_DIM * E_NUM * 2];   // 32 KB; aliased per branch
    const int bid = blockIdx.x;
    const int tid = threadIdx.x;

    if (bid < NB_ROUTER) {
        // ---- router: 8 tokens per block ----
        float* sWr = sbuf;
        float* sWn = sbuf + D_DIM * E_NUM;
        for (int i = tid; i < D_DIM * E_NUM / 4; i += 256) {
            ((float4*)sWr)[i] = ((const float4*)Wr)[i];
            ((float4*)sWn)[i] = ((const float4*)Wn)[i];
        }
        __syncthreads();

        const int w = tid >> 5, lane = tid & 31;
        const int t = bid * 8 + w;
        const float* xr = x + (size_t)t * D_DIM;

        float aR[E_NUM], aN[E_NUM];
#pragma unroll
        for (int e = 0; e < E_NUM; e++) { aR[e] = 0.f; aN[e] = 0.f; }
        for (int d = lane; d < D_DIM; d += 32) {
            float xv = xr[d];
            const float* wr = sWr + d * E_NUM;
            const float* wn = sWn + d * E_NUM;
#pragma unroll
            for (int e = 0; e < E_NUM; e++) {
                aR[e] = fmaf(xv, wr[e], aR[e]);
                aN[e] = fmaf(xv, wn[e], aN[e]);
            }
        }
#pragma unroll
        for (int e = 0; e < E_NUM; e++) {
#pragma unroll
            for (int o = 16; o > 0; o >>= 1) {
                aR[e] += __shfl_xor_sync(0xffffffffu, aR[e], o);
                aN[e] += __shfl_xor_sync(0xffffffffu, aN[e], o);
            }
        }
        if (lane == 0) {
            float nl[E_NUM];
#pragma unroll
            for (int e = 0; e < E_NUM; e++) {
                float nv = aN[e] + bn[e];
                float sp = fmaxf(nv, 0.f) + log1pf(expf(-fabsf(nv)));
                float noise = jax_normal((uint32_t)(t * E_NUM + e));
                nl[e] = aR[e] + br[e] + noise * sp;
            }
            int i0 = 0; float v0 = nl[0];
#pragma unroll
            for (int e = 1; e < E_NUM; e++) if (nl[e] > v0) { v0 = nl[e]; i0 = e; }
            int i1 = -1; float v1 = -3.4e38f;
#pragma unroll
            for (int e = 0; e < E_NUM; e++)
                if (e != i0 && nl[e] > v1) { v1 = nl[e]; i1 = e; }
            float z  = expf(v1 - v0);
            float g0 = 1.f / (1.f + z);
            float g1 = z   / (1.f + z);
            int p0 = atomicAdd(&g_cnt[i0], 1);
            g_tok[i0 * CAP + p0]  = t;
            g_slot[i0 * CAP + p0] = 0;
            g_gate[i0 * CAP + p0] = g0;
            int p1 = atomicAdd(&g_cnt[i1], 1);
            g_tok[i1 * CAP + p1]  = t;
            g_slot[i1 * CAP + p1] = 1;
            g_gate[i1 * CAP + p1] = g1;
        }
    } else if (bid < NB_ROUTER + NB_XSPLIT) {
        // ---- xsplit: fp32 -> fp16, 8 elems/thread ----
        const size_t i = ((size_t)(bid - NB_ROUTER) * 256 + tid) * 8;
        float f[8];
        *(float4*)&f[0] = *(const float4*)(x + i);
        *(float4*)&f[4] = *(const float4*)(x + i + 4);
        *(uint4*)(g_X + i) = pack8_half(f);
    } else if (bid < NB_ROUTER + NB_XSPLIT + NB_W1) {
        // ---- W1 transpose: [e][512][2048] -> [e][2048][512] fp16 ----
        const int idx = bid - (NB_ROUTER + NB_XSPLIT);
        const int e   = idx >> 10;            // / (64*16)
        const int rem = idx & 1023;
        const int n0  = (rem & 63) * 32;      // H_DIM/32 = 64
        const int k0  = (rem >> 6) * 32;
        transpose_tile(W1, g_W1t, D_DIM, H_DIM, e, n0, k0, tid, sbuf);
    } else {
        // ---- W2 transpose: [e][2048][512] -> [e][512][2048] fp16 ----
        const int idx = bid - (NB_ROUTER + NB_XSPLIT + NB_W1);
        const int e   = idx >> 10;
        const int rem = idx & 1023;
        const int n0  = (rem & 15) * 32;      // D_DIM/32 = 16
        const int k0  = (rem >> 4) * 32;
        transpose_tile(W2, g_W2t, H_DIM, D_DIM, e, n0, k0, tid, sbuf);
    }
}

// ---------------- wmma mainloop over one K-chunk held in SMEM ---------------
typedef wmma::fragment<wmma::matrix_a, 16, 16, 16, __half, wmma::row_major> FragA;
typedef wmma::fragment<wmma::matrix_b, 16, 16, 16, __half, wmma::col_major> FragB;
typedef wmma::fragment<wmma::accumulator, 16, 16, 16, float> FragC;

__device__ __forceinline__ void chunk_mma(const char* smem, int m0, int n0w,
                                          FragC acc[2][4]) {
    const __half* A = (const __half*)(smem + OFF_A);
    const __half* B = (const __half*)(smem + OFF_B);
#pragma unroll
    for (int ks = 0; ks < BK; ks += 16) {
        FragA a[2];
#pragma unroll
        for (int i = 0; i < 2; i++)
            wmma::load_matrix_sync(a[i], A + (m0 + 16 * i) * LDA + ks, LDA);
#pragma unroll
        for (int n = 0; n < 4; n++) {
            FragB b;
            wmma::load_matrix_sync(b, B + (n0w + 16 * n) * LDA + ks, LDA);
#pragma unroll
            for (int i = 0; i < 2; i++)
                wmma::mma_sync(acc[i][n], a[i], b, acc[i][n]);
        }
    }
}

// ---------------- GEMM1: H = relu(gather(X) @ W1[e] + b1[e]) ----------------
__global__ __launch_bounds__(256)
void gemm1_kernel(const float* __restrict__ b1) {
    const int e    = blockIdx.z;
    const int M    = g_cnt[e];
    const int row0 = blockIdx.y * BM;
    if (row0 >= M) return;
    const int n0   = blockIdx.x * BN;

    extern __shared__ char smem[];
    const uint32_t sb = smem_to_u32(smem);
    const int tid  = threadIdx.x;
    const int warp = tid >> 5;
    const int wm   = warp >> 1, wn = warp & 1;     // 4x2 warp grid
    const int m0   = wm * 32,   n0w = wn * 64;

    const int lrow = tid >> 1;                     // loader row 0..127
    const int lk   = (tid & 1) * 16;               // loader col offset in chunk

    const int tok = g_tok[e * CAP + row0 + lrow];
    const __half* ap = g_X + (size_t)tok * D_DIM + lk;
    const __half* bp = g_W1t + (size_t)e * H_DIM * D_DIM + (size_t)(n0 + lrow) * D_DIM + lk;

    FragC acc[2][4];
#pragma unroll
    for (int i = 0; i < 2; i++)
#pragma unroll
        for (int n = 0; n < 4; n++) wmma::fill_fragment(acc[i][n], 0.f);

    const uint32_t so = sb + (uint32_t)(lrow * LDA + lk) * 2;

#define G1_LOAD(k0, st) do {                                                \
        uint32_t d_ = so + (st) * STAGE;                                    \
        CP_ASYNC16_CA(d_ + OFF_A,      ap + (k0));                          \
        CP_ASYNC16_CA(d_ + OFF_A + 16, ap + (k0) + 8);                      \
        CP_ASYNC16(d_ + OFF_B,      bp + (k0));                             \
        CP_ASYNC16(d_ + OFF_B + 16, bp + (k0) + 8);                         \
        CP_COMMIT();                                                        \
    } while (0)

    G1_LOAD(0, 0);
    const int NC = D_DIM / BK;   // 16
#pragma unroll 1
    for (int c = 0; c < NC; c++) {
        const int st = c & 1;
        if (c + 1 < NC) { G1_LOAD((c + 1) * BK, st ^ 1); CP_WAIT(1); }
        else            { CP_WAIT(0); }
        __syncthreads();
        chunk_mma(smem + st * STAGE, m0, n0w, acc);
        __syncthreads();
    }

    // epilogue: stage accum to SMEM fp32, then relu+bias -> fp16 H
    float* Cs = (float*)smem;
#pragma unroll
    for (int i = 0; i < 2; i++)
#pragma unroll
        for (int n = 0; n < 4; n++)
            wmma::store_matrix_sync(Cs + (m0 + 16 * i) * LDC + n0w + 16 * n,
                                    acc[i][n], LDC, wmma::mem_row_major);
    __syncthreads();

    const int erow = tid >> 1;
    const int ecol = (tid & 1) * 64;
    const float* b1e = b1 + e * H_DIM + n0 + ecol;
    const size_t hbase = ((size_t)e * CAP + row0 + erow) * H_DIM + n0 + ecol;
#pragma unroll
    for (int q = 0; q < 8; q++) {
        float f[8];
#pragma unroll
        for (int j = 0; j < 8; j++)
            f[j] = fmaxf(Cs[erow * LDC + ecol + q * 8 + j] + __ldg(b1e + q * 8 + j), 0.f);
        *(uint4*)(g_H + hbase + q * 8) = pack8_half(f);
    }
}

// ---------------- GEMM2: Yh[slot][tok] = fp16(gate * (H @ W2[e] + b2[e])) ---
__global__ __launch_bounds__(256)
void gemm2_kernel(const float* __restrict__ b2) {
    const int e    = blockIdx.z;
    const int M    = g_cnt[e];
    const int row0 = blockIdx.y * BM;
    if (row0 >= M) return;
    const int n0   = blockIdx.x * BN;

    extern __shared__ char smem[];
    const uint32_t sb = smem_to_u32(smem);
    const int tid  = threadIdx.x;
    const int warp = tid >> 5;
    const int wm   = warp >> 1, wn = warp & 1;
    const int m0   = wm * 32,   n0w = wn * 64;

    const int lrow = tid >> 1;
    const int lk   = (tid & 1) * 16;

    const __half* ap = g_H + ((size_t)e * CAP + row0 + lrow) * H_DIM + lk;
    const __half* bp = g_W2t + (size_t)e * D_DIM * H_DIM + (size_t)(n0 + lrow) * H_DIM + lk;

    FragC acc[2][4];
#pragma unroll
    for (int i = 0; i < 2; i++)
#pragma unroll
        for (int n = 0; n < 4; n++) wmma::fill_fragment(acc[i][n], 0.f);

    const uint32_t so = sb + (uint32_t)(lrow * LDA + lk) * 2;

#define G2_LOAD(k0, st) do {                                                \
        uint32_t d_ = so + (st) * STAGE;                                    \
        CP_ASYNC16_CA(d_ + OFF_A,      ap + (k0));                          \
        CP_ASYNC16_CA(d_ + OFF_A + 16, ap + (k0) + 8);                      \
        CP_ASYNC16(d_ + OFF_B,      bp + (k0));                             \
        CP_ASYNC16(d_ + OFF_B + 16, bp + (k0) + 8);                         \
        CP_COMMIT();                                                        \
    } while (0)

    G2_LOAD(0, 0);
    const int NC = H_DIM / BK;   // 64
#pragma unroll 1
    for (int c = 0; c < NC; c++) {
        const int st = c & 1;
        if (c + 1 < NC) { G2_LOAD((c + 1) * BK, st ^ 1); CP_WAIT(1); }
        else            { CP_WAIT(0); }
        __syncthreads();
        chunk_mma(smem + st * STAGE, m0, n0w, acc);
        __syncthreads();
    }

    float* Cs = (float*)smem;
#pragma unroll
    for (int i = 0; i < 2; i++)
#pragma unroll
        for (int n = 0; n < 4; n++)
            wmma::store_matrix_sync(Cs + (m0 + 16 * i) * LDC + n0w + 16 * n,
                                    acc[i][n], LDC, wmma::mem_row_major);
    __syncthreads();

    const int erow = tid >> 1;
    const int ecol = (tid & 1) * 64;
    if (row0 + erow < M) {
        const int   tok  = g_tok[e * CAP + row0 + erow];
        const int   slot = g_slot[e * CAP + row0 + erow];
        const float gate = g_gate[e * CAP + row0 + erow];
        const float* b2e = b2 + e * D_DIM + n0 + ecol;
        __half* yp = g_Yh + ((size_t)slot * T_TOK + tok) * D_DIM + n0 + ecol;
#pragma unroll
        for (int q = 0; q < 8; q++) {
            float f[8];
#pragma unroll
            for (int j = 0; j < 8; j++)
                f[j] = gate * (Cs[erow * LDC + ecol + q * 8 + j] + __ldg(b2e + q * 8 + j));
            *(uint4*)(yp + q * 8) = pack8_half(f);
        }
    }
}

// ---------------- combine: out = fp32(Y0) + fp32(Y1) ------------------------
__global__ __launch_bounds__(256)
void combine_kernel(float* __restrict__ out) {
    const size_t i = ((size_t)blockIdx.x * 256 + threadIdx.x) * 8;
    uint4 a4 = *(const uint4*)(g_Yh + i);
    uint4 b4 = *(const uint4*)(g_Yh + (size_t)T_TOK * D_DIM + i);
    const uint32_t* a = (const uint32_t*)&a4;
    const uint32_t* b = (const uint32_t*)&b4;
    float o[8];
#pragma unroll
    for (int j = 0; j < 4; j++) {
        float2 fa = __half22float2(*(const __half2*)&a[j]);
        float2 fb = __half22float2(*(const __half2*)&b[j]);
        o[2 * j]     = fa.x + fb.x;
        o[2 * j + 1] = fa.y + fb.y;
    }
    *(float4*)(out + i)     = *(float4*)&o[0];
    *(float4*)(out + i + 4) = *(float4*)&o[4];
}

// ---------------- launch ---------------------------------------------------
extern "C" void kernel_launch(void* const* d_in, const int* in_sizes, int n_in,
                              void* d_out, int out_size) {
    const float* x  = (const float*)d_in[0];
    const float* Wr = (const float*)d_in[1];
    const float* br = (const float*)d_in[2];
    const float* Wn = (const float*)d_in[3];
    const float* bn = (const float*)d_in[4];
    const float* W1 = (const float*)d_in[5];
    const float* b1 = (const float*)d_in[6];
    const float* W2 = (const float*)d_in[7];
    const float* b2 = (const float*)d_in[8];
    float* out = (float*)d_out;

    cudaFuncSetAttribute(gemm1_kernel, cudaFuncAttributeMaxDynamicSharedMemorySize, SMEM_BYTES);
    cudaFuncSetAttribute(gemm2_kernel, cudaFuncAttributeMaxDynamicSharedMemorySize, SMEM_BYTES);

    void* cntp = nullptr;
    cudaGetSymbolAddress(&cntp, g_cnt);
    cudaMemsetAsync(cntp, 0, sizeof(int) * E_NUM, 0);

    // fused prologue: router + X fp16 prestage + both weight transposes
    prep_kernel<<<NB_TOTAL, 256>>>(x, Wr, br, Wn, bn, W1, W2);

    dim3 grid1(H_DIM / BN, CAP / BM, E_NUM);
    gemm1_kernel<<<grid1, 256, SMEM_BYTES>>>(b1);

    dim3 grid2(D_DIM / BN, CAP / BM, E_NUM);
    gemm2_kernel<<<grid2, 256, SMEM_BYTES>>>(b2);

    combine_kernel<<<T_TOK * D_DIM / (256 * 8), 256>>>(out);
}